// round 1
// baseline (speedup 1.0000x reference)
#include <cuda_runtime.h>

// Problem constants
#define BB 4
#define TT 2048
#define CC 768
#define HH 12
#define DD 64
// B*H*T*D = 6,291,456 ; B*T*C = 6,291,456

__device__ float g_q[BB * HH * TT * DD];
__device__ float g_k[BB * HH * TT * DD];
__device__ float g_v[BB * HH * TT * DD];
__device__ float g_o[BB * TT * CC];

// ---------------------------------------------------------------------------
// QKV GEMM: C[m][n] = sum_k x[m][k] * w_qkv[n][k]
// M = 8192 (b*2048+t), N = 2304 (s*768 + h*64 + d), K = 768
// Epilogue: RoPE on q/k, q pre-scaled by 1/sqrt(D); scatter into g_q/g_k/g_v
// Tiles: 128x128x16, 256 threads, 8x8 micro-tile.
// ---------------------------------------------------------------------------
__global__ __launch_bounds__(256) void qkv_gemm_kernel(
    const float* __restrict__ x, const float* __restrict__ w,
    const float* __restrict__ rsin, const float* __restrict__ rcos)
{
    __shared__ float As[16][128];
    __shared__ float Bs[16][128];

    const int tid = threadIdx.x;
    const int r0 = (tid >> 4) << 3;   // 0..120 step 8
    const int c0 = (tid & 15) << 3;   // 0..120 step 8
    const int mBase = blockIdx.y * 128;
    const int nBase = blockIdx.x * 128;

    float acc[8][8];
#pragma unroll
    for (int i = 0; i < 8; i++)
#pragma unroll
        for (int j = 0; j < 8; j++) acc[i][j] = 0.0f;

    const int lrow = tid >> 2;          // 0..63
    const int lq   = (tid & 3) << 2;    // 0,4,8,12

    for (int kb = 0; kb < 768; kb += 16) {
#pragma unroll
        for (int p = 0; p < 2; p++) {
            const int row = lrow + p * 64;
            float4 av = *(const float4*)(x + (size_t)(mBase + row) * 768 + kb + lq);
            As[lq + 0][row] = av.x; As[lq + 1][row] = av.y;
            As[lq + 2][row] = av.z; As[lq + 3][row] = av.w;
            float4 bv = *(const float4*)(w + (size_t)(nBase + row) * 768 + kb + lq);
            Bs[lq + 0][row] = bv.x; Bs[lq + 1][row] = bv.y;
            Bs[lq + 2][row] = bv.z; Bs[lq + 3][row] = bv.w;
        }
        __syncthreads();
#pragma unroll
        for (int kk = 0; kk < 16; kk++) {
            float4 a0 = *(const float4*)&As[kk][r0];
            float4 a1 = *(const float4*)&As[kk][r0 + 4];
            float4 b0 = *(const float4*)&Bs[kk][c0];
            float4 b1 = *(const float4*)&Bs[kk][c0 + 4];
            float ar[8] = {a0.x, a0.y, a0.z, a0.w, a1.x, a1.y, a1.z, a1.w};
            float br[8] = {b0.x, b0.y, b0.z, b0.w, b1.x, b1.y, b1.z, b1.w};
#pragma unroll
            for (int i = 0; i < 8; i++)
#pragma unroll
                for (int j = 0; j < 8; j++)
                    acc[i][j] += ar[i] * br[j];
        }
        __syncthreads();
    }

    // Epilogue. Whole 128-wide n-block lives in one s (768 % 128 == 0).
    const int s_idx = nBase / 768;
#pragma unroll
    for (int i = 0; i < 8; i++) {
        const int row_g = mBase + r0 + i;
        const int b = row_g >> 11;
        const int t = row_g & 2047;
        if (s_idx < 2) {
            float* dst = (s_idx == 0) ? g_q : g_k;
            const float sc = (s_idx == 0) ? 0.125f : 1.0f;   // 1/sqrt(64) folded into q
#pragma unroll
            for (int j = 0; j < 8; j += 2) {
                const int col_g = nBase + c0 + j;
                const int rem = col_g - s_idx * 768;
                const int h = rem >> 6;
                const int d = rem & 63;
                const float sn = rsin[t * 32 + (d >> 1)];
                const float cs = rcos[t * 32 + (d >> 1)];
                const float v1 = acc[i][j];
                const float v2 = acc[i][j + 1];
                const size_t off = ((size_t)(b * HH + h) * TT + t) * DD + d;
                dst[off]     = (v1 * cs - v2 * sn) * sc;
                dst[off + 1] = (v1 * sn + v2 * cs) * sc;
            }
        } else {
#pragma unroll
            for (int j = 0; j < 8; j++) {
                const int col_g = nBase + c0 + j;
                const int rem = col_g - 1536;
                const int h = rem >> 6;
                const int d = rem & 63;
                g_v[((size_t)(b * HH + h) * TT + t) * DD + d] = acc[i][j];
            }
        }
    }
}

// ---------------------------------------------------------------------------
// Flash attention, fp32, causal. One block = (b,h) x 64 query rows.
// BM=BN=64, D=64. 256 threads: tx(16) over cols/d, ty(16) over rows.
// Smem: Qs[d][r], Vs[c][d], KPs = K[d][c] reused as P[c][r]  -> 48KB static.
// ---------------------------------------------------------------------------
__global__ __launch_bounds__(256) void attn_kernel()
{
    __shared__ float Qs[64 * 64];
    __shared__ float Vs[64 * 64];
    __shared__ float KPs[64 * 64];   // K (transposed) then reused for P

    const int qi = gridDim.x - 1 - blockIdx.x;   // heavy tiles scheduled first
    const int bh = blockIdx.y;                   // 0..47
    const float* qp = g_q + (size_t)bh * TT * DD;
    const float* kp = g_k + (size_t)bh * TT * DD;
    const float* vp = g_v + (size_t)bh * TT * DD;

    const int tid = threadIdx.x;
    const int tx = tid & 15;
    const int ty = tid >> 4;

    // tile loader mapping: 64 rows x 16 float4/row
    const int lf = tid & 15;    // float4 index along d
    const int lr = tid >> 4;    // base row, stride 16

    // Load Q tile transposed: Qs[d][r]
    for (int rr = lr; rr < 64; rr += 16) {
        float4 v = *(const float4*)(qp + (size_t)(qi * 64 + rr) * 64 + 4 * lf);
        Qs[(4 * lf + 0) * 64 + rr] = v.x;
        Qs[(4 * lf + 1) * 64 + rr] = v.y;
        Qs[(4 * lf + 2) * 64 + rr] = v.z;
        Qs[(4 * lf + 3) * 64 + rr] = v.w;
    }

    float m[4], l[4], o[4][4];
#pragma unroll
    for (int j = 0; j < 4; j++) {
        m[j] = -1e30f; l[j] = 0.0f;
#pragma unroll
        for (int i = 0; i < 4; i++) o[j][i] = 0.0f;
    }
    __syncthreads();

    for (int jt = 0; jt <= qi; jt++) {
        // Load K (transposed) + V (natural)
        for (int rr = lr; rr < 64; rr += 16) {
            float4 kv = *(const float4*)(kp + (size_t)(jt * 64 + rr) * 64 + 4 * lf);
            KPs[(4 * lf + 0) * 64 + rr] = kv.x;
            KPs[(4 * lf + 1) * 64 + rr] = kv.y;
            KPs[(4 * lf + 2) * 64 + rr] = kv.z;
            KPs[(4 * lf + 3) * 64 + rr] = kv.w;
            *(float4*)&Vs[rr * 64 + 4 * lf] =
                *(const float4*)(vp + (size_t)(jt * 64 + rr) * 64 + 4 * lf);
        }
        __syncthreads();

        // S = Q K^T (q already scaled)
        float s[4][4];
#pragma unroll
        for (int j = 0; j < 4; j++)
#pragma unroll
            for (int i = 0; i < 4; i++) s[j][i] = 0.0f;
#pragma unroll 16
        for (int kk = 0; kk < 64; kk++) {
            float4 qv = *(const float4*)&Qs[kk * 64 + 4 * ty];
            float4 kv = *(const float4*)&KPs[kk * 64 + 4 * tx];
            float qr[4] = {qv.x, qv.y, qv.z, qv.w};
            float kr[4] = {kv.x, kv.y, kv.z, kv.w};
#pragma unroll
            for (int j = 0; j < 4; j++)
#pragma unroll
                for (int i = 0; i < 4; i++)
                    s[j][i] += qr[j] * kr[i];
        }

        if (jt == qi) {   // diagonal tile: causal mask
#pragma unroll
            for (int j = 0; j < 4; j++)
#pragma unroll
                for (int i = 0; i < 4; i++)
                    if (4 * tx + i > 4 * ty + j) s[j][i] = -1e30f;
        }

        // online softmax update
        float alpha[4];
#pragma unroll
        for (int j = 0; j < 4; j++) {
            float mx = fmaxf(fmaxf(s[j][0], s[j][1]), fmaxf(s[j][2], s[j][3]));
#pragma unroll
            for (int off = 8; off >= 1; off >>= 1)
                mx = fmaxf(mx, __shfl_xor_sync(0xffffffffu, mx, off));
            const float mn = fmaxf(m[j], mx);
            alpha[j] = __expf(m[j] - mn);
            m[j] = mn;
            float rs = 0.0f;
#pragma unroll
            for (int i = 0; i < 4; i++) {
                s[j][i] = __expf(s[j][i] - mn);
                rs += s[j][i];
            }
#pragma unroll
            for (int off = 8; off >= 1; off >>= 1)
                rs += __shfl_xor_sync(0xffffffffu, rs, off);
            l[j] = l[j] * alpha[j] + rs;
        }

        __syncthreads();   // everyone done reading KPs as K

        // P -> smem (KPs reused as P[c][r]); rescale O by alpha
#pragma unroll
        for (int i = 0; i < 4; i++) {
            float4 pv = make_float4(s[0][i], s[1][i], s[2][i], s[3][i]);
            *(float4*)&KPs[(4 * tx + i) * 64 + 4 * ty] = pv;
        }
#pragma unroll
        for (int j = 0; j < 4; j++)
#pragma unroll
            for (int i = 0; i < 4; i++) o[j][i] *= alpha[j];
        __syncthreads();

        // O += P V
#pragma unroll 16
        for (int cc = 0; cc < 64; cc++) {
            float4 pv = *(const float4*)&KPs[cc * 64 + 4 * ty];
            float4 vv = *(const float4*)&Vs[cc * 64 + 4 * tx];
            float pr[4] = {pv.x, pv.y, pv.z, pv.w};
            float vr[4] = {vv.x, vv.y, vv.z, vv.w};
#pragma unroll
            for (int j = 0; j < 4; j++)
#pragma unroll
                for (int i = 0; i < 4; i++)
                    o[j][i] += pr[j] * vr[i];
        }
        __syncthreads();   // before next tile overwrites KPs/Vs
    }

    // write O in [b][t][h*64+d] layout
    const int b = bh / HH;
    const int h = bh % HH;
#pragma unroll
    for (int j = 0; j < 4; j++) {
        const float inv = 1.0f / l[j];
        const int t = qi * 64 + 4 * ty + j;
        float4 ov = make_float4(o[j][0] * inv, o[j][1] * inv,
                                o[j][2] * inv, o[j][3] * inv);
        *(float4*)&g_o[(size_t)(b * TT + t) * CC + h * DD + 4 * tx] = ov;
    }
}

// ---------------------------------------------------------------------------
// Proj GEMM: out[m][n] = sum_k g_o[m][k] * w_proj[n][k]
// M = 8192, N = 768, K = 768. Same tiling as qkv.
// ---------------------------------------------------------------------------
__global__ __launch_bounds__(256) void proj_gemm_kernel(
    float* __restrict__ out, const float* __restrict__ w)
{
    __shared__ float As[16][128];
    __shared__ float Bs[16][128];

    const int tid = threadIdx.x;
    const int r0 = (tid >> 4) << 3;
    const int c0 = (tid & 15) << 3;
    const int mBase = blockIdx.y * 128;
    const int nBase = blockIdx.x * 128;

    float acc[8][8];
#pragma unroll
    for (int i = 0; i < 8; i++)
#pragma unroll
        for (int j = 0; j < 8; j++) acc[i][j] = 0.0f;

    const int lrow = tid >> 2;
    const int lq   = (tid & 3) << 2;

    for (int kb = 0; kb < 768; kb += 16) {
#pragma unroll
        for (int p = 0; p < 2; p++) {
            const int row = lrow + p * 64;
            float4 av = *(const float4*)(g_o + (size_t)(mBase + row) * 768 + kb + lq);
            As[lq + 0][row] = av.x; As[lq + 1][row] = av.y;
            As[lq + 2][row] = av.z; As[lq + 3][row] = av.w;
            float4 bv = *(const float4*)(w + (size_t)(nBase + row) * 768 + kb + lq);
            Bs[lq + 0][row] = bv.x; Bs[lq + 1][row] = bv.y;
            Bs[lq + 2][row] = bv.z; Bs[lq + 3][row] = bv.w;
        }
        __syncthreads();
#pragma unroll
        for (int kk = 0; kk < 16; kk++) {
            float4 a0 = *(const float4*)&As[kk][r0];
            float4 a1 = *(const float4*)&As[kk][r0 + 4];
            float4 b0 = *(const float4*)&Bs[kk][c0];
            float4 b1 = *(const float4*)&Bs[kk][c0 + 4];
            float ar[8] = {a0.x, a0.y, a0.z, a0.w, a1.x, a1.y, a1.z, a1.w};
            float br[8] = {b0.x, b0.y, b0.z, b0.w, b1.x, b1.y, b1.z, b1.w};
#pragma unroll
            for (int i = 0; i < 8; i++)
#pragma unroll
                for (int j = 0; j < 8; j++)
                    acc[i][j] += ar[i] * br[j];
        }
        __syncthreads();
    }

#pragma unroll
    for (int i = 0; i < 8; i++) {
        const int row_g = mBase + r0 + i;
        *(float4*)(out + (size_t)row_g * 768 + nBase + c0) =
            make_float4(acc[i][0], acc[i][1], acc[i][2], acc[i][3]);
        *(float4*)(out + (size_t)row_g * 768 + nBase + c0 + 4) =
            make_float4(acc[i][4], acc[i][5], acc[i][6], acc[i][7]);
    }
}

// ---------------------------------------------------------------------------
extern "C" void kernel_launch(void* const* d_in, const int* in_sizes, int n_in,
                              void* d_out, int out_size)
{
    const float* x      = (const float*)d_in[0];
    const float* w_qkv  = (const float*)d_in[1];
    const float* w_proj = (const float*)d_in[2];
    const float* rsin   = (const float*)d_in[3];
    const float* rcos   = (const float*)d_in[4];
    float* out = (float*)d_out;

    qkv_gemm_kernel<<<dim3(18, 64), 256>>>(x, w_qkv, rsin, rcos);
    attn_kernel<<<dim3(32, 48), 256>>>();
    proj_gemm_kernel<<<dim3(6, 64), 256>>>(out, w_proj);
}

// round 6
// speedup vs baseline: 1.2494x; 1.2494x over previous
#include <cuda_runtime.h>
#include <cuda_bf16.h>
#include <cstdint>

// Problem constants
#define BB 4
#define TT 2048
#define CC 768
#define HH 12
#define DD 64

__device__ float g_q[BB * HH * TT * DD];
__device__ float g_k[BB * HH * TT * DD];
__device__ float g_v[BB * HH * TT * DD];
__device__ float g_o[BB * TT * CC];

static __device__ __forceinline__ uint32_t smem_u32(const void* p) {
    uint32_t a;
    asm("{ .reg .u64 t; cvta.to.shared.u64 t, %1; cvt.u32.u64 %0, t; }"
        : "=r"(a) : "l"(p));
    return a;
}

static __device__ __forceinline__ void ldm4(uint32_t* r, uint32_t addr) {
    asm volatile("ldmatrix.sync.aligned.m8n8.x4.shared.b16 {%0,%1,%2,%3}, [%4];"
                 : "=r"(r[0]), "=r"(r[1]), "=r"(r[2]), "=r"(r[3]) : "r"(addr));
}

static __device__ __forceinline__ void mma16816(float* d, const uint32_t* a,
                                                const uint32_t* b) {
    asm volatile(
        "mma.sync.aligned.m16n8k16.row.col.f32.bf16.bf16.f32 "
        "{%0,%1,%2,%3}, {%4,%5,%6,%7}, {%8,%9}, {%0,%1,%2,%3};"
        : "+f"(d[0]), "+f"(d[1]), "+f"(d[2]), "+f"(d[3])
        : "r"(a[0]), "r"(a[1]), "r"(a[2]), "r"(a[3]), "r"(b[0]), "r"(b[1]));
}

// ===========================================================================
// Split-bf16 HMMA GEMM: D[m][n] = sum_k A[m][k] * B[n][k]  (fp32-accurate)
// 128x128 tile, 8 warps (2 m x 4 n), each warp 64x32 via 4x4 m16n8k16 frags.
// K-chunk 32; smem rows padded to 80B (conflict-free ldmatrix).
//   sA_hi[128][40]bf16 | sA_lo | sB_hi | sB_lo  -> 40960B static smem.
// Per chunk: 3 MMAs per (mt,nt,khalf): hi*hi + hi*lo + lo*hi.
// EPI 0: qkv epilogue (RoPE scatter, q scaled 0.125)   A=x,   B=w_qkv
// EPI 1: proj epilogue (plain store)                   A=g_o, B=w_proj
// ===========================================================================
#define STRIDE_B 80          // bytes per smem row (40 bf16)
#define TILE_BYTES 10240     // 128 * 80
#define NCHUNK 24            // 768 / 32

template <int EPI>
__global__ __launch_bounds__(256) void gemm_mma_kernel(
    const float* __restrict__ Am, const float* __restrict__ Bm,
    const float* __restrict__ rsin, const float* __restrict__ rcos,
    float* __restrict__ outp)
{
    __shared__ __align__(16) char smem[4 * TILE_BYTES];
    const uint32_t sb = smem_u32(smem);
    const uint32_t sA_hi = sb, sA_lo = sb + TILE_BYTES;
    const uint32_t sB_hi = sb + 2 * TILE_BYTES, sB_lo = sb + 3 * TILE_BYTES;

    const int tid = threadIdx.x;
    const int lane = tid & 31, warp = tid >> 5;
    const int warpM = warp & 1, warpN = warp >> 1;   // 2 x 4 warps
    const int mBase = blockIdx.y * 128, nBase = blockIdx.x * 128;

    // ---- loader mapping: one 128-row x 32-k chunk row per thread ----
    const float* Abase = (EPI == 0) ? Am : g_o;
    const bool isB = tid >= 128;
    const int lrow = tid & 127;
    const float* srow = isB ? (Bm + (size_t)(nBase + lrow) * 768)
                            : (Abase + (size_t)(mBase + lrow) * 768);
    const uint32_t st_hi = (isB ? sB_hi : sA_hi) + (uint32_t)lrow * STRIDE_B;
    const uint32_t st_lo = st_hi + 2 * TILE_BYTES -
                           (isB ? 0u : 0u) - TILE_BYTES + TILE_BYTES; // = hi+TILE
    const uint32_t st_lo2 = st_hi + TILE_BYTES;

    // ---- ldmatrix per-lane address offsets ----
    // A frag (mt, kh): mat0 m0-7/k0-7, mat1 m8-15/k0-7, mat2 m0-7/k8-15, mat3 m8-15/k8-15
    const uint32_t aoff =
        (uint32_t)(warpM * 64 + (lane & 7) + ((lane >> 3) & 1) * 8) * STRIDE_B +
        ((lane >> 4) & 1) * 16;
    // B frag pair p (ntiles 2p,2p+1): mat0 n0-7/k0-7, mat1 n0-7/k8-15,
    //                                 mat2 n8-15/k0-7, mat3 n8-15/k8-15
    const uint32_t boff =
        (uint32_t)(warpN * 32 + (lane & 7) + ((lane >> 4) & 1) * 8) * STRIDE_B +
        ((lane >> 3) & 1) * 16;

    float acc[4][4][4];
#pragma unroll
    for (int mt = 0; mt < 4; mt++)
#pragma unroll
        for (int nt = 0; nt < 4; nt++)
#pragma unroll
            for (int r = 0; r < 4; r++) acc[mt][nt][r] = 0.0f;

    for (int c = 0; c < NCHUNK; c++) {
        // ---- load chunk: 32 fp32 -> 32 hi bf16 + 32 lo bf16 per row ----
        {
            const float* p = srow + c * 32;
#pragma unroll
            for (int g = 0; g < 4; g++) {
                float4 x0 = *(const float4*)(p + g * 8);
                float4 x1 = *(const float4*)(p + g * 8 + 4);
                float f[8] = {x0.x, x0.y, x0.z, x0.w, x1.x, x1.y, x1.z, x1.w};
                uint32_t hi[4], lo[4];
#pragma unroll
                for (int q = 0; q < 4; q++) {
                    __nv_bfloat16 h0 = __float2bfloat16(f[2 * q]);
                    __nv_bfloat16 h1 = __float2bfloat16(f[2 * q + 1]);
                    __nv_bfloat16 l0 = __float2bfloat16(f[2 * q] - __bfloat162float(h0));
                    __nv_bfloat16 l1 = __float2bfloat16(f[2 * q + 1] - __bfloat162float(h1));
                    __nv_bfloat162 hh = __halves2bfloat162(h0, h1);
                    __nv_bfloat162 ll = __halves2bfloat162(l0, l1);
                    hi[q] = *reinterpret_cast<uint32_t*>(&hh);
                    lo[q] = *reinterpret_cast<uint32_t*>(&ll);
                }
                asm volatile("st.shared.v4.b32 [%0], {%1,%2,%3,%4};" ::
                             "r"(st_hi + g * 16), "r"(hi[0]), "r"(hi[1]),
                             "r"(hi[2]), "r"(hi[3]) : "memory");
                asm volatile("st.shared.v4.b32 [%0], {%1,%2,%3,%4};" ::
                             "r"(st_lo2 + g * 16), "r"(lo[0]), "r"(lo[1]),
                             "r"(lo[2]), "r"(lo[3]) : "memory");
            }
        }
        __syncthreads();

        // ---- compute: 2 k-halves of 16 ----
#pragma unroll
        for (int kh = 0; kh < 2; kh++) {
            const uint32_t khb = kh * 32;
            uint32_t bh[2][4], bl[2][4];
#pragma unroll
            for (int p = 0; p < 2; p++) {
                ldm4(bh[p], sB_hi + boff + p * (16 * STRIDE_B) + khb);
                ldm4(bl[p], sB_lo + boff + p * (16 * STRIDE_B) + khb);
            }
#pragma unroll
            for (int mt = 0; mt < 4; mt++) {
                uint32_t ah[4], al[4];
                ldm4(ah, sA_hi + aoff + mt * (16 * STRIDE_B) + khb);
                ldm4(al, sA_lo + aoff + mt * (16 * STRIDE_B) + khb);
#pragma unroll
                for (int nt = 0; nt < 4; nt++) {
                    const uint32_t* bhf = &bh[nt >> 1][(nt & 1) * 2];
                    const uint32_t* blf = &bl[nt >> 1][(nt & 1) * 2];
                    mma16816(acc[mt][nt], ah, bhf);
                    mma16816(acc[mt][nt], ah, blf);
                    mma16816(acc[mt][nt], al, bhf);
                }
            }
        }
        __syncthreads();
    }

    // ---- epilogue: thread holds D[m = base + l/4 (+8)][n = base + 2*(l%4) + {0,1}] ----
    const int gRow = lane >> 2;
    const int gCol = (lane & 3) * 2;
#pragma unroll
    for (int mt = 0; mt < 4; mt++) {
#pragma unroll
        for (int half = 0; half < 2; half++) {   // regs {0,1} row r, {2,3} row r+8
            const int row_g = mBase + warpM * 64 + mt * 16 + gRow + half * 8;
#pragma unroll
            for (int nt = 0; nt < 4; nt++) {
                const float v1 = acc[mt][nt][half * 2];
                const float v2 = acc[mt][nt][half * 2 + 1];
                const int col_g = nBase + warpN * 32 + nt * 8 + gCol;
                if (EPI == 0) {
                    const int b = row_g >> 11, t = row_g & 2047;
                    const int s_idx = nBase / 768;
                    const int rem = col_g - s_idx * 768;
                    const int h = rem >> 6, d = rem & 63;
                    const size_t off = ((size_t)(b * HH + h) * TT + t) * DD + d;
                    if (s_idx < 2) {
                        float* dst = (s_idx == 0) ? g_q : g_k;
                        const float sc = (s_idx == 0) ? 0.125f : 1.0f;
                        const float sn = rsin[t * 32 + (d >> 1)];
                        const float cs = rcos[t * 32 + (d >> 1)];
                        *(float2*)(dst + off) =
                            make_float2((v1 * cs - v2 * sn) * sc,
                                        (v1 * sn + v2 * cs) * sc);
                    } else {
                        *(float2*)(g_v + off) = make_float2(v1, v2);
                    }
                } else {
                    *(float2*)(outp + (size_t)row_g * 768 + col_g) =
                        make_float2(v1, v2);
                }
            }
        }
    }
}

// ---------------------------------------------------------------------------
// Flash attention, fp32, causal (unchanged from passing round-1 kernel).
// ---------------------------------------------------------------------------
__global__ __launch_bounds__(256) void attn_kernel()
{
    __shared__ float Qs[64 * 64];
    __shared__ float Vs[64 * 64];
    __shared__ float KPs[64 * 64];   // K (transposed) then reused for P

    const int qi = gridDim.x - 1 - blockIdx.x;   // heavy tiles scheduled first
    const int bh = blockIdx.y;                   // 0..47
    const float* qp = g_q + (size_t)bh * TT * DD;
    const float* kp = g_k + (size_t)bh * TT * DD;
    const float* vp = g_v + (size_t)bh * TT * DD;

    const int tid = threadIdx.x;
    const int tx = tid & 15;
    const int ty = tid >> 4;

    const int lf = tid & 15;
    const int lr = tid >> 4;

    for (int rr = lr; rr < 64; rr += 16) {
        float4 v = *(const float4*)(qp + (size_t)(qi * 64 + rr) * 64 + 4 * lf);
        Qs[(4 * lf + 0) * 64 + rr] = v.x;
        Qs[(4 * lf + 1) * 64 + rr] = v.y;
        Qs[(4 * lf + 2) * 64 + rr] = v.z;
        Qs[(4 * lf + 3) * 64 + rr] = v.w;
    }

    float m[4], l[4], o[4][4];
#pragma unroll
    for (int j = 0; j < 4; j++) {
        m[j] = -1e30f; l[j] = 0.0f;
#pragma unroll
        for (int i = 0; i < 4; i++) o[j][i] = 0.0f;
    }
    __syncthreads();

    for (int jt = 0; jt <= qi; jt++) {
        for (int rr = lr; rr < 64; rr += 16) {
            float4 kv = *(const float4*)(kp + (size_t)(jt * 64 + rr) * 64 + 4 * lf);
            KPs[(4 * lf + 0) * 64 + rr] = kv.x;
            KPs[(4 * lf + 1) * 64 + rr] = kv.y;
            KPs[(4 * lf + 2) * 64 + rr] = kv.z;
            KPs[(4 * lf + 3) * 64 + rr] = kv.w;
            *(float4*)&Vs[rr * 64 + 4 * lf] =
                *(const float4*)(vp + (size_t)(jt * 64 + rr) * 64 + 4 * lf);
        }
        __syncthreads();

        float s[4][4];
#pragma unroll
        for (int j = 0; j < 4; j++)
#pragma unroll
            for (int i = 0; i < 4; i++) s[j][i] = 0.0f;
#pragma unroll 16
        for (int kk = 0; kk < 64; kk++) {
            float4 qv = *(const float4*)&Qs[kk * 64 + 4 * ty];
            float4 kv = *(const float4*)&KPs[kk * 64 + 4 * tx];
            float qr[4] = {qv.x, qv.y, qv.z, qv.w};
            float kr[4] = {kv.x, kv.y, kv.z, kv.w};
#pragma unroll
            for (int j = 0; j < 4; j++)
#pragma unroll
                for (int i = 0; i < 4; i++)
                    s[j][i] += qr[j] * kr[i];
        }

        if (jt == qi) {
#pragma unroll
            for (int j = 0; j < 4; j++)
#pragma unroll
                for (int i = 0; i < 4; i++)
                    if (4 * tx + i > 4 * ty + j) s[j][i] = -1e30f;
        }

        float alpha[4];
#pragma unroll
        for (int j = 0; j < 4; j++) {
            float mx = fmaxf(fmaxf(s[j][0], s[j][1]), fmaxf(s[j][2], s[j][3]));
#pragma unroll
            for (int off = 8; off >= 1; off >>= 1)
                mx = fmaxf(mx, __shfl_xor_sync(0xffffffffu, mx, off));
            const float mn = fmaxf(m[j], mx);
            alpha[j] = __expf(m[j] - mn);
            m[j] = mn;
            float rs = 0.0f;
#pragma unroll
            for (int i = 0; i < 4; i++) {
                s[j][i] = __expf(s[j][i] - mn);
                rs += s[j][i];
            }
#pragma unroll
            for (int off = 8; off >= 1; off >>= 1)
                rs += __shfl_xor_sync(0xffffffffu, rs, off);
            l[j] = l[j] * alpha[j] + rs;
        }

        __syncthreads();

#pragma unroll
        for (int i = 0; i < 4; i++) {
            float4 pv = make_float4(s[0][i], s[1][i], s[2][i], s[3][i]);
            *(float4*)&KPs[(4 * tx + i) * 64 + 4 * ty] = pv;
        }
#pragma unroll
        for (int j = 0; j < 4; j++)
#pragma unroll
            for (int i = 0; i < 4; i++) o[j][i] *= alpha[j];
        __syncthreads();

#pragma unroll 16
        for (int cc = 0; cc < 64; cc++) {
            float4 pv = *(const float4*)&KPs[cc * 64 + 4 * ty];
            float4 vv = *(const float4*)&Vs[cc * 64 + 4 * tx];
            float pr[4] = {pv.x, pv.y, pv.z, pv.w};
            float vr[4] = {vv.x, vv.y, vv.z, vv.w};
#pragma unroll
            for (int j = 0; j < 4; j++)
#pragma unroll
                for (int i = 0; i < 4; i++)
                    o[j][i] += pr[j] * vr[i];
        }
        __syncthreads();
    }

    const int b = bh / HH;
    const int h = bh % HH;
#pragma unroll
    for (int j = 0; j < 4; j++) {
        const float inv = 1.0f / l[j];
        const int t = qi * 64 + 4 * ty + j;
        float4 ov = make_float4(o[j][0] * inv, o[j][1] * inv,
                                o[j][2] * inv, o[j][3] * inv);
        *(float4*)&g_o[(size_t)(b * TT + t) * CC + h * DD + 4 * tx] = ov;
    }
}

// ---------------------------------------------------------------------------
extern "C" void kernel_launch(void* const* d_in, const int* in_sizes, int n_in,
                              void* d_out, int out_size)
{
    const float* x      = (const float*)d_in[0];
    const float* w_qkv  = (const float*)d_in[1];
    const float* w_proj = (const float*)d_in[2];
    const float* rsin   = (const float*)d_in[3];
    const float* rcos   = (const float*)d_in[4];
    float* out = (float*)d_out;

    // QKV: M=8192, N=2304  -> grid (18, 64)
    gemm_mma_kernel<0><<<dim3(18, 64), 256>>>(x, w_qkv, rsin, rcos, nullptr);
    // Attention over g_q/g_k/g_v -> g_o
    attn_kernel<<<dim3(32, 48), 256>>>();
    // Proj: M=8192, N=768 -> grid (6, 64)
    gemm_mma_kernel<1><<<dim3(6, 64), 256>>>(nullptr, w_proj, rsin, rcos, out);
}

// round 7
// speedup vs baseline: 1.9923x; 1.5946x over previous
#include <cuda_runtime.h>
#include <cuda_bf16.h>
#include <cstdint>

// Problem constants
#define BB 4
#define TT 2048
#define CC 768
#define HH 12
#define DD 64

__device__ float g_q[BB * HH * TT * DD];
__device__ float g_k[BB * HH * TT * DD];
__device__ float g_v[BB * HH * TT * DD];
__device__ float g_o[BB * TT * CC];

static __device__ __forceinline__ uint32_t smem_u32(const void* p) {
    uint32_t a;
    asm("{ .reg .u64 t; cvta.to.shared.u64 t, %1; cvt.u32.u64 %0, t; }"
        : "=r"(a) : "l"(p));
    return a;
}

static __device__ __forceinline__ void ldm4(uint32_t* r, uint32_t addr) {
    asm volatile("ldmatrix.sync.aligned.m8n8.x4.shared.b16 {%0,%1,%2,%3}, [%4];"
                 : "=r"(r[0]), "=r"(r[1]), "=r"(r[2]), "=r"(r[3]) : "r"(addr));
}

static __device__ __forceinline__ void mma16816(float* d, const uint32_t* a,
                                                const uint32_t* b) {
    asm volatile(
        "mma.sync.aligned.m16n8k16.row.col.f32.bf16.bf16.f32 "
        "{%0,%1,%2,%3}, {%4,%5,%6,%7}, {%8,%9}, {%0,%1,%2,%3};"
        : "+f"(d[0]), "+f"(d[1]), "+f"(d[2]), "+f"(d[3])
        : "r"(a[0]), "r"(a[1]), "r"(a[2]), "r"(a[3]), "r"(b[0]), "r"(b[1]));
}

// fp32 -> bf16 hi/lo split helpers
static __device__ __forceinline__ void split2(float f0, float f1,
                                              uint32_t& hi, uint32_t& lo) {
    __nv_bfloat16 h0 = __float2bfloat16(f0);
    __nv_bfloat16 h1 = __float2bfloat16(f1);
    __nv_bfloat16 l0 = __float2bfloat16(f0 - __bfloat162float(h0));
    __nv_bfloat16 l1 = __float2bfloat16(f1 - __bfloat162float(h1));
    __nv_bfloat162 hh = __halves2bfloat162(h0, h1);
    __nv_bfloat162 ll = __halves2bfloat162(l0, l1);
    hi = *reinterpret_cast<uint32_t*>(&hh);
    lo = *reinterpret_cast<uint32_t*>(&ll);
}

// FMA-pipe exp2 (no MUFU). Valid for x <= 0; clamps at -126.
static __device__ __forceinline__ float exp2f_fast(float x) {
    x = fmaxf(x, -126.0f);
    float z = x + 12582912.0f;                       // round-to-nearest-int
    int i = __float_as_int(z) - 0x4B400000;
    float f = x - (z - 12582912.0f);                 // f in [-0.5, 0.5]
    float p = 0.00133336f;
    p = fmaf(p, f, 0.00961813f);
    p = fmaf(p, f, 0.05550411f);
    p = fmaf(p, f, 0.24022651f);
    p = fmaf(p, f, 0.69314718f);
    p = fmaf(p, f, 1.0f);
    return p * __int_as_float((i + 127) << 23);
}
#define L2E 1.4426950408889634f

// ===========================================================================
// Split-bf16 HMMA GEMM (unchanged from round-6 pass)
// ===========================================================================
#define STRIDE_B 80
#define TILE_BYTES 10240
#define NCHUNK 24

template <int EPI>
__global__ __launch_bounds__(256) void gemm_mma_kernel(
    const float* __restrict__ Am, const float* __restrict__ Bm,
    const float* __restrict__ rsin, const float* __restrict__ rcos,
    float* __restrict__ outp)
{
    __shared__ __align__(16) char smem[4 * TILE_BYTES];
    const uint32_t sb = smem_u32(smem);
    const uint32_t sA_hi = sb, sA_lo = sb + TILE_BYTES;
    const uint32_t sB_hi = sb + 2 * TILE_BYTES, sB_lo = sb + 3 * TILE_BYTES;

    const int tid = threadIdx.x;
    const int lane = tid & 31, warp = tid >> 5;
    const int warpM = warp & 1, warpN = warp >> 1;
    const int mBase = blockIdx.y * 128, nBase = blockIdx.x * 128;

    const float* Abase = (EPI == 0) ? Am : g_o;
    const bool isB = tid >= 128;
    const int lrow = tid & 127;
    const float* srow = isB ? (Bm + (size_t)(nBase + lrow) * 768)
                            : (Abase + (size_t)(mBase + lrow) * 768);
    const uint32_t st_hi = (isB ? sB_hi : sA_hi) + (uint32_t)lrow * STRIDE_B;
    const uint32_t st_lo2 = st_hi + TILE_BYTES;

    const uint32_t aoff =
        (uint32_t)(warpM * 64 + (lane & 7) + ((lane >> 3) & 1) * 8) * STRIDE_B +
        ((lane >> 4) & 1) * 16;
    const uint32_t boff =
        (uint32_t)(warpN * 32 + (lane & 7) + ((lane >> 4) & 1) * 8) * STRIDE_B +
        ((lane >> 3) & 1) * 16;

    float acc[4][4][4];
#pragma unroll
    for (int mt = 0; mt < 4; mt++)
#pragma unroll
        for (int nt = 0; nt < 4; nt++)
#pragma unroll
            for (int r = 0; r < 4; r++) acc[mt][nt][r] = 0.0f;

    for (int c = 0; c < NCHUNK; c++) {
        {
            const float* p = srow + c * 32;
#pragma unroll
            for (int g = 0; g < 4; g++) {
                float4 x0 = *(const float4*)(p + g * 8);
                float4 x1 = *(const float4*)(p + g * 8 + 4);
                uint32_t hi[4], lo[4];
                split2(x0.x, x0.y, hi[0], lo[0]);
                split2(x0.z, x0.w, hi[1], lo[1]);
                split2(x1.x, x1.y, hi[2], lo[2]);
                split2(x1.z, x1.w, hi[3], lo[3]);
                asm volatile("st.shared.v4.b32 [%0], {%1,%2,%3,%4};" ::
                             "r"(st_hi + g * 16), "r"(hi[0]), "r"(hi[1]),
                             "r"(hi[2]), "r"(hi[3]) : "memory");
                asm volatile("st.shared.v4.b32 [%0], {%1,%2,%3,%4};" ::
                             "r"(st_lo2 + g * 16), "r"(lo[0]), "r"(lo[1]),
                             "r"(lo[2]), "r"(lo[3]) : "memory");
            }
        }
        __syncthreads();

#pragma unroll
        for (int kh = 0; kh < 2; kh++) {
            const uint32_t khb = kh * 32;
            uint32_t bh[2][4], bl[2][4];
#pragma unroll
            for (int p = 0; p < 2; p++) {
                ldm4(bh[p], sB_hi + boff + p * (16 * STRIDE_B) + khb);
                ldm4(bl[p], sB_lo + boff + p * (16 * STRIDE_B) + khb);
            }
#pragma unroll
            for (int mt = 0; mt < 4; mt++) {
                uint32_t ah[4], al[4];
                ldm4(ah, sA_hi + aoff + mt * (16 * STRIDE_B) + khb);
                ldm4(al, sA_lo + aoff + mt * (16 * STRIDE_B) + khb);
#pragma unroll
                for (int nt = 0; nt < 4; nt++) {
                    const uint32_t* bhf = &bh[nt >> 1][(nt & 1) * 2];
                    const uint32_t* blf = &bl[nt >> 1][(nt & 1) * 2];
                    mma16816(acc[mt][nt], ah, bhf);
                    mma16816(acc[mt][nt], ah, blf);
                    mma16816(acc[mt][nt], al, bhf);
                }
            }
        }
        __syncthreads();
    }

    const int gRow = lane >> 2;
    const int gCol = (lane & 3) * 2;
#pragma unroll
    for (int mt = 0; mt < 4; mt++) {
#pragma unroll
        for (int half = 0; half < 2; half++) {
            const int row_g = mBase + warpM * 64 + mt * 16 + gRow + half * 8;
#pragma unroll
            for (int nt = 0; nt < 4; nt++) {
                const float v1 = acc[mt][nt][half * 2];
                const float v2 = acc[mt][nt][half * 2 + 1];
                const int col_g = nBase + warpN * 32 + nt * 8 + gCol;
                if (EPI == 0) {
                    const int b = row_g >> 11, t = row_g & 2047;
                    const int s_idx = nBase / 768;
                    const int rem = col_g - s_idx * 768;
                    const int h = rem >> 6, d = rem & 63;
                    const size_t off = ((size_t)(b * HH + h) * TT + t) * DD + d;
                    if (s_idx < 2) {
                        float* dst = (s_idx == 0) ? g_q : g_k;
                        const float sc = (s_idx == 0) ? 0.125f : 1.0f;
                        const float sn = rsin[t * 32 + (d >> 1)];
                        const float cs = rcos[t * 32 + (d >> 1)];
                        *(float2*)(dst + off) =
                            make_float2((v1 * cs - v2 * sn) * sc,
                                        (v1 * sn + v2 * cs) * sc);
                    } else {
                        *(float2*)(g_v + off) = make_float2(v1, v2);
                    }
                } else {
                    *(float2*)(outp + (size_t)row_g * 768 + col_g) =
                        make_float2(v1, v2);
                }
            }
        }
    }
}

// ===========================================================================
// Flash attention with split-bf16 HMMA.
// CTA = (b,h) x 128 q rows. 8 warps x 16 rows. K-tile 64 keys.
// Smem (36864B): Q staging hi/lo [128][KST] overlaid by
//   Khi[64][KST] | Klo | Vthi[64 d][KST] | Vtlo   (KST = 144B padded rows)
// Q frags persist in regs. S = QhKh + QhKl + QlKh ; O += PhVh + PhVl + PlVh.
// exp via FMA-pipe exp2. q pre-scaled by 1/sqrt(D) in qkv epilogue.
// ===========================================================================
#define KST 144

__global__ __launch_bounds__(256) void attn_mma_kernel()
{
    __shared__ __align__(16) char smem[36864];
    const uint32_t sb = smem_u32(smem);
    const uint32_t sKhi = sb, sKlo = sb + 9216;
    const uint32_t sVhi = sb + 18432, sVlo = sb + 27648;

    const int tid = threadIdx.x, lane = tid & 31, warp = tid >> 5;
    const int qi = gridDim.x - 1 - blockIdx.x;     // heavy tiles first
    const int bh = blockIdx.y;
    const float* qp = g_q + (size_t)bh * TT * DD;
    const float* kp = g_k + (size_t)bh * TT * DD;
    const float* vp = g_v + (size_t)bh * TT * DD;
    const int qBase = qi * 128;

    // ---- stage Q tile (128 x 64 fp32 -> bf16 hi/lo) ----
    {
        const int row = tid >> 1, half = tid & 1;
        const float* p = qp + (size_t)(qBase + row) * 64 + half * 32;
        const uint32_t dh = sb + (uint32_t)row * KST + half * 64;
        const uint32_t dl = dh + 18432;
#pragma unroll
        for (int g = 0; g < 4; g++) {
            float4 x0 = *(const float4*)(p + g * 8);
            float4 x1 = *(const float4*)(p + g * 8 + 4);
            uint32_t hi[4], lo[4];
            split2(x0.x, x0.y, hi[0], lo[0]);
            split2(x0.z, x0.w, hi[1], lo[1]);
            split2(x1.x, x1.y, hi[2], lo[2]);
            split2(x1.z, x1.w, hi[3], lo[3]);
            asm volatile("st.shared.v4.b32 [%0], {%1,%2,%3,%4};" ::
                         "r"(dh + g * 16), "r"(hi[0]), "r"(hi[1]),
                         "r"(hi[2]), "r"(hi[3]) : "memory");
            asm volatile("st.shared.v4.b32 [%0], {%1,%2,%3,%4};" ::
                         "r"(dl + g * 16), "r"(lo[0]), "r"(lo[1]),
                         "r"(lo[2]), "r"(lo[3]) : "memory");
        }
    }
    __syncthreads();

    // ---- Q fragments: warp rows warp*16..+15, k = d (4 halves of 16) ----
    uint32_t qh[4][4], ql[4][4];
    {
        const uint32_t aoff = sb +
            (uint32_t)(warp * 16 + (lane & 7) + ((lane >> 3) & 1) * 8) * KST +
            ((lane >> 4) & 1) * 16;
#pragma unroll
        for (int kh = 0; kh < 4; kh++) {
            ldm4(qh[kh], aoff + kh * 32);
            ldm4(ql[kh], aoff + 18432 + kh * 32);
        }
    }
    __syncthreads();   // staging consumed; buffers now K/Vt

    float o[8][4];
#pragma unroll
    for (int dn = 0; dn < 8; dn++)
#pragma unroll
        for (int r = 0; r < 4; r++) o[dn][r] = 0.0f;
    float mrow[2] = {-1e30f, -1e30f};
    float lrow[2] = {0.0f, 0.0f};

    const int lkey = tid & 63, lpart = tid >> 6;   // loader: key x 16-d part
    const uint32_t boff =
        (uint32_t)((lane & 7) + ((lane >> 4) & 1) * 8) * KST +
        ((lane >> 3) & 1) * 16;
    const int jtEnd = 2 * qi + 1;

    for (int jt = 0; jt <= jtEnd; jt++) {
        // ---- load K tile rows=key (hi/lo) ----
        {
            const float* p = kp + (size_t)(jt * 64 + lkey) * 64 + lpart * 16;
            const uint32_t dh = sKhi + (uint32_t)lkey * KST + lpart * 32;
            const uint32_t dl = dh + 9216;
#pragma unroll
            for (int g = 0; g < 2; g++) {
                float4 x0 = *(const float4*)(p + g * 8);
                float4 x1 = *(const float4*)(p + g * 8 + 4);
                uint32_t hi[4], lo[4];
                split2(x0.x, x0.y, hi[0], lo[0]);
                split2(x0.z, x0.w, hi[1], lo[1]);
                split2(x1.x, x1.y, hi[2], lo[2]);
                split2(x1.z, x1.w, hi[3], lo[3]);
                asm volatile("st.shared.v4.b32 [%0], {%1,%2,%3,%4};" ::
                             "r"(dh + g * 16), "r"(hi[0]), "r"(hi[1]),
                             "r"(hi[2]), "r"(hi[3]) : "memory");
                asm volatile("st.shared.v4.b32 [%0], {%1,%2,%3,%4};" ::
                             "r"(dl + g * 16), "r"(lo[0]), "r"(lo[1]),
                             "r"(lo[2]), "r"(lo[3]) : "memory");
            }
        }
        // ---- load V tile transposed: Vt[d][key] (hi/lo) ----
        {
            const float* p = vp + (size_t)(jt * 64 + lkey) * 64 + lpart * 16;
#pragma unroll
            for (int g = 0; g < 4; g++) {
                float4 x = *(const float4*)(p + g * 4);
                float f[4] = {x.x, x.y, x.z, x.w};
#pragma unroll
                for (int e = 0; e < 4; e++) {
                    const int d = lpart * 16 + g * 4 + e;
                    __nv_bfloat16 h = __float2bfloat16(f[e]);
                    __nv_bfloat16 l = __float2bfloat16(f[e] - __bfloat162float(h));
                    *(__nv_bfloat16*)(smem + 18432 + d * KST + lkey * 2) = h;
                    *(__nv_bfloat16*)(smem + 27648 + d * KST + lkey * 2) = l;
                }
            }
        }
        __syncthreads();

        // ---- S = Q K^T  (16 x 64 per warp) ----
        float s[8][4];
#pragma unroll
        for (int nt = 0; nt < 8; nt++)
#pragma unroll
            for (int r = 0; r < 4; r++) s[nt][r] = 0.0f;
#pragma unroll
        for (int kh = 0; kh < 4; kh++) {
#pragma unroll
            for (int p = 0; p < 4; p++) {
                uint32_t kbh[4], kbl[4];
                ldm4(kbh, sKhi + boff + p * (16 * KST) + kh * 32);
                ldm4(kbl, sKlo + boff + p * (16 * KST) + kh * 32);
#pragma unroll
                for (int sub = 0; sub < 2; sub++) {
                    float* d = s[2 * p + sub];
                    mma16816(d, qh[kh], &kbh[sub * 2]);
                    mma16816(d, qh[kh], &kbl[sub * 2]);
                    mma16816(d, ql[kh], &kbh[sub * 2]);
                }
            }
        }

        // ---- causal mask on diagonal tiles ----
        if (jt >= 2 * qi) {
            const int row0 = qBase + warp * 16 + (lane >> 2);
            const int colb = jt * 64 + 2 * (lane & 3);
#pragma unroll
            for (int nt = 0; nt < 8; nt++) {
                const int c = colb + nt * 8;
#pragma unroll
                for (int r = 0; r < 4; r++) {
                    const int row = row0 + ((r >> 1) << 3);
                    const int col = c + (r & 1);
                    if (col > row) s[nt][r] = -1e30f;
                }
            }
        }

        // ---- online softmax (rows r, r+8; 4 lanes share a row) ----
        float mx0 = -1e30f, mx1 = -1e30f;
#pragma unroll
        for (int nt = 0; nt < 8; nt++) {
            mx0 = fmaxf(mx0, fmaxf(s[nt][0], s[nt][1]));
            mx1 = fmaxf(mx1, fmaxf(s[nt][2], s[nt][3]));
        }
        mx0 = fmaxf(mx0, __shfl_xor_sync(0xffffffffu, mx0, 1));
        mx0 = fmaxf(mx0, __shfl_xor_sync(0xffffffffu, mx0, 2));
        mx1 = fmaxf(mx1, __shfl_xor_sync(0xffffffffu, mx1, 1));
        mx1 = fmaxf(mx1, __shfl_xor_sync(0xffffffffu, mx1, 2));
        const float mn0 = fmaxf(mrow[0], mx0);
        const float mn1 = fmaxf(mrow[1], mx1);
        const float a0 = exp2f_fast((mrow[0] - mn0) * L2E);
        const float a1 = exp2f_fast((mrow[1] - mn1) * L2E);
        mrow[0] = mn0; mrow[1] = mn1;
        float rs0 = 0.0f, rs1 = 0.0f;
#pragma unroll
        for (int nt = 0; nt < 8; nt++) {
            s[nt][0] = exp2f_fast((s[nt][0] - mn0) * L2E);
            s[nt][1] = exp2f_fast((s[nt][1] - mn0) * L2E);
            s[nt][2] = exp2f_fast((s[nt][2] - mn1) * L2E);
            s[nt][3] = exp2f_fast((s[nt][3] - mn1) * L2E);
            rs0 += s[nt][0] + s[nt][1];
            rs1 += s[nt][2] + s[nt][3];
        }
        rs0 += __shfl_xor_sync(0xffffffffu, rs0, 1);
        rs0 += __shfl_xor_sync(0xffffffffu, rs0, 2);
        rs1 += __shfl_xor_sync(0xffffffffu, rs1, 1);
        rs1 += __shfl_xor_sync(0xffffffffu, rs1, 2);
        lrow[0] = lrow[0] * a0 + rs0;
        lrow[1] = lrow[1] * a1 + rs1;
#pragma unroll
        for (int dn = 0; dn < 8; dn++) {
            o[dn][0] *= a0; o[dn][1] *= a0;
            o[dn][2] *= a1; o[dn][3] *= a1;
        }

        // ---- O += P V  (P frags direct from S accumulators) ----
#pragma unroll
        for (int kh = 0; kh < 4; kh++) {      // 16-key halves
            uint32_t ph[4], pl[4];
#pragma unroll
            for (int idx = 0; idx < 4; idx++) {
                const int nt = 2 * kh + (idx >> 1);
                const int rb = (idx & 1) * 2;
                split2(s[nt][rb], s[nt][rb + 1], ph[idx], pl[idx]);
            }
#pragma unroll
            for (int p = 0; p < 4; p++) {     // d-tile pairs
                uint32_t vbh[4], vbl[4];
                ldm4(vbh, sVhi + boff + p * (16 * KST) + kh * 32);
                ldm4(vbl, sVlo + boff + p * (16 * KST) + kh * 32);
#pragma unroll
                for (int sub = 0; sub < 2; sub++) {
                    float* d = o[2 * p + sub];
                    mma16816(d, ph, &vbh[sub * 2]);
                    mma16816(d, ph, &vbl[sub * 2]);
                    mma16816(d, pl, &vbh[sub * 2]);
                }
            }
        }
        __syncthreads();   // before next tile overwrites K/Vt
    }

    // ---- write O: g_o[b][t][h*64 + d] ----
    const int b = bh / HH, h = bh % HH;
    const float inv0 = 1.0f / lrow[0];
    const float inv1 = 1.0f / lrow[1];
    const int row0 = qBase + warp * 16 + (lane >> 2);
    const int colb = h * 64 + 2 * (lane & 3);
#pragma unroll
    for (int dn = 0; dn < 8; dn++) {
        const int col = colb + dn * 8;
        *(float2*)&g_o[(size_t)(b * TT + row0) * CC + col] =
            make_float2(o[dn][0] * inv0, o[dn][1] * inv0);
        *(float2*)&g_o[(size_t)(b * TT + row0 + 8) * CC + col] =
            make_float2(o[dn][2] * inv1, o[dn][3] * inv1);
    }
}

// ---------------------------------------------------------------------------
extern "C" void kernel_launch(void* const* d_in, const int* in_sizes, int n_in,
                              void* d_out, int out_size)
{
    const float* x      = (const float*)d_in[0];
    const float* w_qkv  = (const float*)d_in[1];
    const float* w_proj = (const float*)d_in[2];
    const float* rsin   = (const float*)d_in[3];
    const float* rcos   = (const float*)d_in[4];
    float* out = (float*)d_out;

    // QKV: M=8192, N=2304  -> grid (18, 64)
    gemm_mma_kernel<0><<<dim3(18, 64), 256>>>(x, w_qkv, rsin, rcos, nullptr);
    // Attention: 16 q-tiles of 128 x 48 (b,h)
    attn_mma_kernel<<<dim3(16, 48), 256>>>();
    // Proj: M=8192, N=768 -> grid (6, 64)
    gemm_mma_kernel<1><<<dim3(6, 64), 256>>>(nullptr, w_proj, rsin, rcos, out);
}

// round 8
// speedup vs baseline: 2.2218x; 1.1152x over previous
#include <cuda_runtime.h>
#include <cuda_bf16.h>
#include <cstdint>

// Problem constants
#define BB 4
#define TT 2048
#define CC 768
#define HH 12
#define DD 64
#define NQ (BB * HH * TT * DD)

// Pre-split bf16 hi/lo intermediates (producer writes split once)
__device__ __nv_bfloat16 g_qh[NQ], g_ql[NQ];
__device__ __nv_bfloat16 g_kh[NQ], g_kl[NQ];
__device__ __nv_bfloat16 g_vh[NQ], g_vl[NQ];
__device__ __nv_bfloat16 g_oh[BB * TT * CC], g_ol[BB * TT * CC];

static __device__ __forceinline__ uint32_t smem_u32(const void* p) {
    uint32_t a;
    asm("{ .reg .u64 t; cvta.to.shared.u64 t, %1; cvt.u32.u64 %0, t; }"
        : "=r"(a) : "l"(p));
    return a;
}

static __device__ __forceinline__ void ldm4(uint32_t* r, uint32_t addr) {
    asm volatile("ldmatrix.sync.aligned.m8n8.x4.shared.b16 {%0,%1,%2,%3}, [%4];"
                 : "=r"(r[0]), "=r"(r[1]), "=r"(r[2]), "=r"(r[3]) : "r"(addr));
}
static __device__ __forceinline__ void ldm4t(uint32_t* r, uint32_t addr) {
    asm volatile("ldmatrix.sync.aligned.m8n8.x4.trans.shared.b16 {%0,%1,%2,%3}, [%4];"
                 : "=r"(r[0]), "=r"(r[1]), "=r"(r[2]), "=r"(r[3]) : "r"(addr));
}

static __device__ __forceinline__ void mma16816(float* d, const uint32_t* a,
                                                const uint32_t* b) {
    asm volatile(
        "mma.sync.aligned.m16n8k16.row.col.f32.bf16.bf16.f32 "
        "{%0,%1,%2,%3}, {%4,%5,%6,%7}, {%8,%9}, {%0,%1,%2,%3};"
        : "+f"(d[0]), "+f"(d[1]), "+f"(d[2]), "+f"(d[3])
        : "r"(a[0]), "r"(a[1]), "r"(a[2]), "r"(a[3]), "r"(b[0]), "r"(b[1]));
}

static __device__ __forceinline__ void split2(float f0, float f1,
                                              uint32_t& hi, uint32_t& lo) {
    __nv_bfloat16 h0 = __float2bfloat16(f0);
    __nv_bfloat16 h1 = __float2bfloat16(f1);
    __nv_bfloat16 l0 = __float2bfloat16(f0 - __bfloat162float(h0));
    __nv_bfloat16 l1 = __float2bfloat16(f1 - __bfloat162float(h1));
    __nv_bfloat162 hh = __halves2bfloat162(h0, h1);
    __nv_bfloat162 ll = __halves2bfloat162(l0, l1);
    hi = *reinterpret_cast<uint32_t*>(&hh);
    lo = *reinterpret_cast<uint32_t*>(&ll);
}

// FMA-pipe exp2 (no MUFU). Valid for x <= 0; clamps at -126.
static __device__ __forceinline__ float exp2f_fast(float x) {
    x = fmaxf(x, -126.0f);
    float z = x + 12582912.0f;
    int i = __float_as_int(z) - 0x4B400000;
    float f = x - (z - 12582912.0f);
    float p = 0.00133336f;
    p = fmaf(p, f, 0.00961813f);
    p = fmaf(p, f, 0.05550411f);
    p = fmaf(p, f, 0.24022651f);
    p = fmaf(p, f, 0.69314718f);
    p = fmaf(p, f, 1.0f);
    return p * __int_as_float((i + 127) << 23);
}
#define L2E 1.4426950408889634f

#define STS4(addr, a, b, c, d) \
    asm volatile("st.shared.v4.b32 [%0], {%1,%2,%3,%4};" :: \
                 "r"(addr), "r"(a), "r"(b), "r"(c), "r"(d) : "memory")

// ===========================================================================
// Split-bf16 HMMA GEMM. EPI 0: A=x fp32 (split on load), RoPE epilogue ->
// g_{q,k,v}{h,l}. EPI 1: A = pre-split g_oh/g_ol (pure copy), plain store.
// B always fp32 (split on load).
// ===========================================================================
#define STRIDE_B 80
#define TILE_BYTES 10240
#define NCHUNK 24

template <int EPI>
__global__ __launch_bounds__(256) void gemm_mma_kernel(
    const float* __restrict__ Am, const float* __restrict__ Bm,
    const float* __restrict__ rsin, const float* __restrict__ rcos,
    float* __restrict__ outp)
{
    __shared__ __align__(16) char smem[4 * TILE_BYTES];
    const uint32_t sb = smem_u32(smem);
    const uint32_t sA_hi = sb, sB_hi = sb + 2 * TILE_BYTES;

    const int tid = threadIdx.x;
    const int lane = tid & 31, warp = tid >> 5;
    const int warpM = warp & 1, warpN = warp >> 1;
    const int mBase = blockIdx.y * 128, nBase = blockIdx.x * 128;

    const bool isB = tid >= 128;
    const int lrow = tid & 127;
    const float* srow32 = isB ? (Bm + (size_t)(nBase + lrow) * 768)
                              : (Am + (size_t)(mBase + lrow) * 768);
    const __nv_bfloat16* srow16h = g_oh + (size_t)(mBase + lrow) * 768;
    const __nv_bfloat16* srow16l = g_ol + (size_t)(mBase + lrow) * 768;
    const uint32_t st_hi = (isB ? sB_hi : sA_hi) + (uint32_t)lrow * STRIDE_B;
    const uint32_t st_lo = st_hi + TILE_BYTES;

    const uint32_t aoff =
        (uint32_t)(warpM * 64 + (lane & 7) + ((lane >> 3) & 1) * 8) * STRIDE_B +
        ((lane >> 4) & 1) * 16;
    const uint32_t boff =
        (uint32_t)(warpN * 32 + (lane & 7) + ((lane >> 4) & 1) * 8) * STRIDE_B +
        ((lane >> 3) & 1) * 16;

    float acc[4][4][4];
#pragma unroll
    for (int mt = 0; mt < 4; mt++)
#pragma unroll
        for (int nt = 0; nt < 4; nt++)
#pragma unroll
            for (int r = 0; r < 4; r++) acc[mt][nt][r] = 0.0f;

    for (int c = 0; c < NCHUNK; c++) {
        if (EPI == 1 && !isB) {
            // pre-split A: pure bf16 copy (32 k-values = 4 x 16B per tile)
            const uint4* ph = (const uint4*)(srow16h + c * 32);
            const uint4* pl = (const uint4*)(srow16l + c * 32);
#pragma unroll
            for (int g = 0; g < 4; g++) {
                uint4 h = ph[g], l = pl[g];
                STS4(st_hi + g * 16, h.x, h.y, h.z, h.w);
                STS4(st_lo + g * 16, l.x, l.y, l.z, l.w);
            }
        } else {
            const float* p = srow32 + c * 32;
#pragma unroll
            for (int g = 0; g < 4; g++) {
                float4 x0 = *(const float4*)(p + g * 8);
                float4 x1 = *(const float4*)(p + g * 8 + 4);
                uint32_t hi[4], lo[4];
                split2(x0.x, x0.y, hi[0], lo[0]);
                split2(x0.z, x0.w, hi[1], lo[1]);
                split2(x1.x, x1.y, hi[2], lo[2]);
                split2(x1.z, x1.w, hi[3], lo[3]);
                STS4(st_hi + g * 16, hi[0], hi[1], hi[2], hi[3]);
                STS4(st_lo + g * 16, lo[0], lo[1], lo[2], lo[3]);
            }
        }
        __syncthreads();

#pragma unroll
        for (int kh = 0; kh < 2; kh++) {
            const uint32_t khb = kh * 32;
            uint32_t bh[2][4], bl[2][4];
#pragma unroll
            for (int p = 0; p < 2; p++) {
                ldm4(bh[p], sB_hi + boff + p * (16 * STRIDE_B) + khb);
                ldm4(bl[p], sB_hi + TILE_BYTES + boff + p * (16 * STRIDE_B) + khb);
            }
#pragma unroll
            for (int mt = 0; mt < 4; mt++) {
                uint32_t ah[4], al[4];
                ldm4(ah, sA_hi + aoff + mt * (16 * STRIDE_B) + khb);
                ldm4(al, sA_hi + TILE_BYTES + aoff + mt * (16 * STRIDE_B) + khb);
#pragma unroll
                for (int nt = 0; nt < 4; nt++) {
                    const uint32_t* bhf = &bh[nt >> 1][(nt & 1) * 2];
                    const uint32_t* blf = &bl[nt >> 1][(nt & 1) * 2];
                    mma16816(acc[mt][nt], ah, bhf);
                    mma16816(acc[mt][nt], ah, blf);
                    mma16816(acc[mt][nt], al, bhf);
                }
            }
        }
        __syncthreads();
    }

    const int gRow = lane >> 2;
    const int gCol = (lane & 3) * 2;
#pragma unroll
    for (int mt = 0; mt < 4; mt++) {
#pragma unroll
        for (int half = 0; half < 2; half++) {
            const int row_g = mBase + warpM * 64 + mt * 16 + gRow + half * 8;
#pragma unroll
            for (int nt = 0; nt < 4; nt++) {
                const float v1 = acc[mt][nt][half * 2];
                const float v2 = acc[mt][nt][half * 2 + 1];
                const int col_g = nBase + warpN * 32 + nt * 8 + gCol;
                if (EPI == 0) {
                    const int b = row_g >> 11, t = row_g & 2047;
                    const int s_idx = nBase / 768;
                    const int rem = col_g - s_idx * 768;
                    const int h = rem >> 6, d = rem & 63;
                    const size_t off = ((size_t)(b * HH + h) * TT + t) * DD + d;
                    uint32_t hi, lo;
                    if (s_idx < 2) {
                        const float sc = (s_idx == 0) ? 0.125f : 1.0f;
                        const float sn = rsin[t * 32 + (d >> 1)];
                        const float cs = rcos[t * 32 + (d >> 1)];
                        split2((v1 * cs - v2 * sn) * sc,
                               (v1 * sn + v2 * cs) * sc, hi, lo);
                        __nv_bfloat16* dh = (s_idx == 0) ? g_qh : g_kh;
                        __nv_bfloat16* dl = (s_idx == 0) ? g_ql : g_kl;
                        *(uint32_t*)(dh + off) = hi;
                        *(uint32_t*)(dl + off) = lo;
                    } else {
                        split2(v1, v2, hi, lo);
                        *(uint32_t*)(g_vh + off) = hi;
                        *(uint32_t*)(g_vl + off) = lo;
                    }
                } else {
                    *(float2*)(outp + (size_t)row_g * 768 + col_g) =
                        make_float2(v1, v2);
                }
            }
        }
    }
}

// ===========================================================================
// Flash attention, split-bf16 HMMA, pre-split operands.
// CTA = (b,h) x 128 q rows; 8 warps x 16 rows; K-tile 64 keys.
// Smem 36864B, 144B row stride (conflict-free ldmatrix):
//   Khi[64] | Klo | Vhi[64] | Vlo  (K,V natural [key][d])
//   overlaid at start by Qhi[128] | Qlo[128] staging.
// V B-fragments via ldmatrix.x4.trans (no smem transpose).
// Output written pre-split to g_oh/g_ol.
// ===========================================================================
#define KST 144

__global__ __launch_bounds__(256) void attn_mma_kernel()
{
    __shared__ __align__(16) char smem[36864];
    const uint32_t sb = smem_u32(smem);
    const uint32_t sKhi = sb, sKlo = sb + 9216;
    const uint32_t sVhi = sb + 18432, sVlo = sb + 27648;

    const int tid = threadIdx.x, lane = tid & 31, warp = tid >> 5;
    const int qi = gridDim.x - 1 - blockIdx.x;
    const int bh = blockIdx.y;
    const size_t bhOff = (size_t)bh * TT * DD;
    const int qBase = qi * 128;

    // ---- stage Q (bf16 copy): rows 128 x 128B, stride 144 ----
    {
        const int row = tid >> 1, half = tid & 1;
        const uint4* ph = (const uint4*)(g_qh + bhOff + (size_t)(qBase + row) * 64 + half * 32);
        const uint4* pl = (const uint4*)(g_ql + bhOff + (size_t)(qBase + row) * 64 + half * 32);
        const uint32_t dh = sb + (uint32_t)row * KST + half * 64;
#pragma unroll
        for (int g = 0; g < 4; g++) {
            uint4 h = ph[g], l = pl[g];
            STS4(dh + g * 16, h.x, h.y, h.z, h.w);
            STS4(dh + 18432 + g * 16, l.x, l.y, l.z, l.w);
        }
    }
    __syncthreads();

    uint32_t qh[4][4], ql[4][4];
    {
        const uint32_t aoff = sb +
            (uint32_t)(warp * 16 + (lane & 7) + ((lane >> 3) & 1) * 8) * KST +
            ((lane >> 4) & 1) * 16;
#pragma unroll
        for (int kh = 0; kh < 4; kh++) {
            ldm4(qh[kh], aoff + kh * 32);
            ldm4(ql[kh], aoff + 18432 + kh * 32);
        }
    }
    __syncthreads();

    float o[8][4];
#pragma unroll
    for (int dn = 0; dn < 8; dn++)
#pragma unroll
        for (int r = 0; r < 4; r++) o[dn][r] = 0.0f;
    float mrow[2] = {-1e30f, -1e30f};
    float lrow[2] = {0.0f, 0.0f};

    // K-frag (non-trans, rows=key as "n"): and V-frag (trans, rows=key as "k")
    const uint32_t boff =
        (uint32_t)((lane & 7) + ((lane >> 4) & 1) * 8) * KST +
        ((lane >> 3) & 1) * 16;
    const uint32_t voff =
        (uint32_t)((lane & 7) + ((lane >> 3) & 1) * 8) * KST +
        ((lane >> 4) & 1) * 16;
    const int jtEnd = 2 * qi + 1;

    for (int jt = 0; jt <= jtEnd; jt++) {
        // ---- copy K,V tiles (bf16, natural [key][d]) ----
        {
            const size_t src0 = bhOff + (size_t)jt * 64 * 64;
#pragma unroll
            for (int g = 0; g < 2; g++) {
                const int id = tid + g * 256;
                const int row = id >> 3, part = id & 7;
                const size_t s = src0 + (size_t)row * 64 + part * 8;
                const uint32_t d = (uint32_t)row * KST + part * 16;
                uint4 v;
                v = *(const uint4*)(g_kh + s); STS4(sKhi + d, v.x, v.y, v.z, v.w);
                v = *(const uint4*)(g_kl + s); STS4(sKlo + d, v.x, v.y, v.z, v.w);
                v = *(const uint4*)(g_vh + s); STS4(sVhi + d, v.x, v.y, v.z, v.w);
                v = *(const uint4*)(g_vl + s); STS4(sVlo + d, v.x, v.y, v.z, v.w);
            }
        }
        __syncthreads();

        // ---- S = Q K^T ----
        float s[8][4];
#pragma unroll
        for (int nt = 0; nt < 8; nt++)
#pragma unroll
            for (int r = 0; r < 4; r++) s[nt][r] = 0.0f;
#pragma unroll
        for (int kh = 0; kh < 4; kh++) {
#pragma unroll
            for (int p = 0; p < 4; p++) {
                uint32_t kbh[4], kbl[4];
                ldm4(kbh, sKhi + boff + p * (16 * KST) + kh * 32);
                ldm4(kbl, sKlo + boff + p * (16 * KST) + kh * 32);
#pragma unroll
                for (int sub = 0; sub < 2; sub++) {
                    float* d = s[2 * p + sub];
                    mma16816(d, qh[kh], &kbh[sub * 2]);
                    mma16816(d, qh[kh], &kbl[sub * 2]);
                    mma16816(d, ql[kh], &kbh[sub * 2]);
                }
            }
        }

        if (jt >= 2 * qi) {
            const int row0 = qBase + warp * 16 + (lane >> 2);
            const int colb = jt * 64 + 2 * (lane & 3);
#pragma unroll
            for (int nt = 0; nt < 8; nt++) {
                const int c = colb + nt * 8;
#pragma unroll
                for (int r = 0; r < 4; r++) {
                    const int row = row0 + ((r >> 1) << 3);
                    const int col = c + (r & 1);
                    if (col > row) s[nt][r] = -1e30f;
                }
            }
        }

        // ---- online softmax ----
        float mx0 = -1e30f, mx1 = -1e30f;
#pragma unroll
        for (int nt = 0; nt < 8; nt++) {
            mx0 = fmaxf(mx0, fmaxf(s[nt][0], s[nt][1]));
            mx1 = fmaxf(mx1, fmaxf(s[nt][2], s[nt][3]));
        }
        mx0 = fmaxf(mx0, __shfl_xor_sync(0xffffffffu, mx0, 1));
        mx0 = fmaxf(mx0, __shfl_xor_sync(0xffffffffu, mx0, 2));
        mx1 = fmaxf(mx1, __shfl_xor_sync(0xffffffffu, mx1, 1));
        mx1 = fmaxf(mx1, __shfl_xor_sync(0xffffffffu, mx1, 2));
        const float mn0 = fmaxf(mrow[0], mx0);
        const float mn1 = fmaxf(mrow[1], mx1);
        const float a0 = exp2f_fast((mrow[0] - mn0) * L2E);
        const float a1 = exp2f_fast((mrow[1] - mn1) * L2E);
        mrow[0] = mn0; mrow[1] = mn1;
        float rs0 = 0.0f, rs1 = 0.0f;
#pragma unroll
        for (int nt = 0; nt < 8; nt++) {
            s[nt][0] = exp2f_fast((s[nt][0] - mn0) * L2E);
            s[nt][1] = exp2f_fast((s[nt][1] - mn0) * L2E);
            s[nt][2] = exp2f_fast((s[nt][2] - mn1) * L2E);
            s[nt][3] = exp2f_fast((s[nt][3] - mn1) * L2E);
            rs0 += s[nt][0] + s[nt][1];
            rs1 += s[nt][2] + s[nt][3];
        }
        rs0 += __shfl_xor_sync(0xffffffffu, rs0, 1);
        rs0 += __shfl_xor_sync(0xffffffffu, rs0, 2);
        rs1 += __shfl_xor_sync(0xffffffffu, rs1, 1);
        rs1 += __shfl_xor_sync(0xffffffffu, rs1, 2);
        lrow[0] = lrow[0] * a0 + rs0;
        lrow[1] = lrow[1] * a1 + rs1;
#pragma unroll
        for (int dn = 0; dn < 8; dn++) {
            o[dn][0] *= a0; o[dn][1] *= a0;
            o[dn][2] *= a1; o[dn][3] *= a1;
        }

        // ---- O += P V  (V frags via ldmatrix.trans on natural layout) ----
#pragma unroll
        for (int kh = 0; kh < 4; kh++) {
            uint32_t ph[4], pl[4];
#pragma unroll
            for (int idx = 0; idx < 4; idx++) {
                const int nt = 2 * kh + (idx >> 1);
                const int rb = (idx & 1) * 2;
                split2(s[nt][rb], s[nt][rb + 1], ph[idx], pl[idx]);
            }
#pragma unroll
            for (int p = 0; p < 4; p++) {
                uint32_t vbh[4], vbl[4];
                ldm4t(vbh, sVhi + voff + kh * (16 * KST) + p * 32);
                ldm4t(vbl, sVlo + voff + kh * (16 * KST) + p * 32);
#pragma unroll
                for (int sub = 0; sub < 2; sub++) {
                    float* d = o[2 * p + sub];
                    mma16816(d, ph, &vbh[sub * 2]);
                    mma16816(d, ph, &vbl[sub * 2]);
                    mma16816(d, pl, &vbh[sub * 2]);
                }
            }
        }
        __syncthreads();
    }

    // ---- write O pre-split: g_oh/g_ol [b][t][h*64+d] ----
    const int b = bh / HH, h = bh % HH;
    const float inv0 = 1.0f / lrow[0];
    const float inv1 = 1.0f / lrow[1];
    const int row0 = qBase + warp * 16 + (lane >> 2);
    const int colb = h * 64 + 2 * (lane & 3);
#pragma unroll
    for (int dn = 0; dn < 8; dn++) {
        const int col = colb + dn * 8;
        uint32_t hi, lo;
        split2(o[dn][0] * inv0, o[dn][1] * inv0, hi, lo);
        *(uint32_t*)(g_oh + (size_t)(b * TT + row0) * CC + col) = hi;
        *(uint32_t*)(g_ol + (size_t)(b * TT + row0) * CC + col) = lo;
        split2(o[dn][2] * inv1, o[dn][3] * inv1, hi, lo);
        *(uint32_t*)(g_oh + (size_t)(b * TT + row0 + 8) * CC + col) = hi;
        *(uint32_t*)(g_ol + (size_t)(b * TT + row0 + 8) * CC + col) = lo;
    }
}

// ---------------------------------------------------------------------------
extern "C" void kernel_launch(void* const* d_in, const int* in_sizes, int n_in,
                              void* d_out, int out_size)
{
    const float* x      = (const float*)d_in[0];
    const float* w_qkv  = (const float*)d_in[1];
    const float* w_proj = (const float*)d_in[2];
    const float* rsin   = (const float*)d_in[3];
    const float* rcos   = (const float*)d_in[4];
    float* out = (float*)d_out;

    gemm_mma_kernel<0><<<dim3(18, 64), 256>>>(x, w_qkv, rsin, rcos, nullptr);
    attn_mma_kernel<<<dim3(16, 48), 256>>>();
    gemm_mma_kernel<1><<<dim3(6, 64), 256>>>(nullptr, w_proj, rsin, rcos, out);
}